// round 9
// baseline (speedup 1.0000x reference)
#include <cuda_runtime.h>
#include <cuda_bf16.h>
#include <cuda_fp8.h>
#include <math.h>
#include <stdint.h>

// ---------------------------------------------------------------------------
// Intention_PS_LSTM on GB300: fp8 e4m3 mma.sync path (m16n8k32, sm_89+ PTX).
// gates[8192,2048] = h[8192,512] @ Whh^T ; per CTA: M=128, N=128(4g x 32u), K=512.
// Scaling: W quantized x64, h stored x16 (exact powers of 2), acc / 1024.
// 256 threads, 2 CTAs/SM, 3-stage cp.async pipeline, 4 chunks of K=128.
// ---------------------------------------------------------------------------

#define HID   512
#define F_IN  4
#define MAXB  8192
#define BH    ((size_t)MAXB * HID)
#define WSZ   (4 * HID * HID)          // one Whh: 2048*512

#define SWZ(x) ((x) ^ ((((uint32_t)(x)) >> 3) & 0x70))

// smem byte offsets (tiles 1024-aligned)
#define SM_WX     0                    // float4[128]  = 2048
#define SM_BS     2048                 // float[128]   = 512
#define SM_XS     2560                 // float4[128]  = 2048
#define SM_A(s)   (8192  + (s) * 16384)    // 128 x 128B per stage
#define SM_B(s)   (57344 + (s) * 16384)    // 128 x 128B per stage
#define SM_TOTAL  106496

#define W_SCALE   64.0f
#define H_SCALE   16.0f
#define ACC_INV   (1.0f / (64.0f * 16.0f))
#define H_INV     (1.0f / 16.0f)

__device__ __align__(16) uint8_t g_wb[3 * WSZ];      // e4m3 Whh*64: s,p,d
__device__ __align__(16) uint8_t g_h[4 * BH];        // encoder h*16: ping*2+z
__device__ __align__(16) float   g_c[2 * BH];        // encoder c: z
__device__ __align__(16) uint8_t g_hd[2 * BH];       // decoder h*16 ping-pong
__device__ __align__(16) float   g_cd[BH];           // decoder c
__device__ __align__(16) float   g_lastpos[MAXB * F_IN];

__device__ __forceinline__ float tanh_f(float x) {
    float y;
    asm("tanh.approx.f32 %0, %1;" : "=f"(y) : "f"(x));
    return y;
}
__device__ __forceinline__ float sigm_(float x) {
    return fmaf(tanh_f(0.5f * x), 0.5f, 0.5f);
}
__device__ __forceinline__ uint16_t f2_e4m3x2(float lo, float hi) {
    uint16_t v;
    asm("cvt.rn.satfinite.e4m3x2.f32 %0, %1, %2;" : "=h"(v) : "f"(hi), "f"(lo));
    return v;
}
__device__ __forceinline__ float e4m3_f(uint8_t v) {
    return (float)(*reinterpret_cast<const __nv_fp8_e4m3*>(&v));
}

__device__ __forceinline__ uint32_t smem_u32(const void* p) {
    uint32_t a;
    asm("{ .reg .u64 t; cvta.to.shared.u64 t, %1; cvt.u32.u64 %0, t; }" : "=r"(a) : "l"(p));
    return a;
}
__device__ __forceinline__ void cp16(uint32_t s, const void* g) {
    asm volatile("cp.async.cg.shared.global [%0], [%1], 16;" :: "r"(s), "l"(g));
}
#define CP_COMMIT() asm volatile("cp.async.commit_group;" ::: "memory")
#define CP_WAIT1()  asm volatile("cp.async.wait_group 1;" ::: "memory")
#define CP_WAIT0()  asm volatile("cp.async.wait_group 0;" ::: "memory")

__device__ __forceinline__ void ldsm4(uint32_t* r, uint32_t addr) {
    asm volatile("ldmatrix.sync.aligned.m8n8.x4.shared.b16 {%0,%1,%2,%3}, [%4];"
                 : "=r"(r[0]), "=r"(r[1]), "=r"(r[2]), "=r"(r[3]) : "r"(addr));
}
__device__ __forceinline__ void mma_fp8(float* d, const uint32_t* a, const uint32_t* b) {
    asm volatile("mma.sync.aligned.m16n8k32.row.col.f32.e4m3.e4m3.f32 "
                 "{%0,%1,%2,%3}, {%4,%5,%6,%7}, {%8,%9}, {%0,%1,%2,%3};"
                 : "+f"(d[0]), "+f"(d[1]), "+f"(d[2]), "+f"(d[3])
                 : "r"(a[0]), "r"(a[1]), "r"(a[2]), "r"(a[3]), "r"(b[0]), "r"(b[1]));
}

// ---------------------------------------------------------------------------
__global__ void init_kernel(const float* __restrict__ ws,
                            const float* __restrict__ wp,
                            const float* __restrict__ wd)
{
    size_t i = (size_t)blockIdx.x * blockDim.x + threadIdx.x;
    size_t stride = (size_t)gridDim.x * blockDim.x;
    for (size_t k = i; k < 3 * (size_t)WSZ; k += stride) {
        size_t w = k / WSZ, r = k % WSZ;
        const float* src = (w == 0) ? ws : (w == 1) ? wp : wd;
        __nv_fp8_e4m3 q(src[r] * W_SCALE);
        g_wb[k] = *reinterpret_cast<uint8_t*>(&q);
    }
    for (size_t k = i; k < 2 * BH; k += stride) {
        g_h[k] = 0;       // e4m3 zero is bit pattern 0
        g_c[k] = 0.f;
    }
}

// ---------------------------------------------------------------------------
struct StepParams {
    const float* xA; const float* xB;   // per-z input; NULL => g_lastpos
    int x_stride; int x_off;
    const float* WihA; const float* WihB;
    const float* bihA; const float* bihB;
    const float* bhhA; const float* bhhB;
    int wsel;                           // Whh base: encoder 0 (+z), decoder 2
    int ping; int is_dec;
};

__device__ __forceinline__ void load_chunk(uint32_t Ab, uint32_t Bb,
                                           const uint8_t* __restrict__ hin,
                                           const uint8_t* __restrict__ Whh,
                                           int m_base, int jbase, int kf, int tid)
{
    #pragma unroll
    for (int it = 0; it < 4; it++) {                    // A: 128 rows x 8 x 16B
        int idx = tid + it * 256;
        int row = idx >> 3, c16 = idx & 7;
        cp16(Ab + SWZ(row * 128 + c16 * 16),
             hin + (size_t)(m_base + row) * HID + kf + c16 * 16);
    }
    #pragma unroll
    for (int it = 0; it < 4; it++) {                    // B: 128 rows x 8 x 16B
        int idx = tid + it * 256;
        int row = idx >> 3, c16 = idx & 7;
        int g = row >> 5, jj = row & 31;
        cp16(Bb + SWZ(row * 128 + c16 * 16),
             Whh + (size_t)(g * HID + jbase + jj) * HID + kf + c16 * 16);
    }
}

__global__ __launch_bounds__(256, 2) void lstm_mma_step(StepParams p)
{
    extern __shared__ char smem[];
    const uint32_t sb = smem_u32(smem);
    const int tid  = threadIdx.x;
    const int wid  = tid >> 5, lane = tid & 31;
    const int z    = blockIdx.z;
    const int warp_m = wid & 1;        // 2 m-groups of 64 rows
    const int warp_n = wid >> 1;       // 4 n-groups of 8 units

    const float* __restrict__ Wih = z ? p.WihB : p.WihA;
    const float* __restrict__ bih = z ? p.bihB : p.bihA;
    const float* __restrict__ bhh = z ? p.bhhB : p.bhhA;
    const float* __restrict__ xin = z ? p.xB : p.xA;
    const uint8_t* __restrict__ Whh = g_wb + (size_t)(p.wsel + z) * WSZ;

    const uint8_t* __restrict__ hin;
    uint8_t* __restrict__ hout;
    float* __restrict__ cio;
    if (p.is_dec) {
        hin  = g_hd + (size_t)p.ping * BH;
        hout = g_hd + (size_t)(p.ping ^ 1) * BH;
        cio  = g_cd;
        if (!xin) xin = g_lastpos;
    } else {
        hin  = g_h + (size_t)(p.ping * 2 + z) * BH;
        hout = g_h + (size_t)((p.ping ^ 1) * 2 + z) * BH;
        cio  = g_c + (size_t)z * BH;
    }

    const int m_base = blockIdx.y * 128;
    const int jbase  = blockIdx.x * 32;

    float4* Wx = (float4*)(smem + SM_WX);
    float*  Bs = (float*)(smem + SM_BS);
    float4* Xs = (float4*)(smem + SM_XS);

    if (tid < 128) {
        int g = tid >> 5, u = tid & 31;
        int gr = g * HID + jbase + u;
        Bs[tid] = bih[gr] + bhh[gr];
        Wx[tid] = *(const float4*)(Wih + (size_t)gr * F_IN);
    } else {
        int r = tid - 128;
        Xs[r] = *(const float4*)(xin + (size_t)(m_base + r) * p.x_stride + p.x_off);
    }

    // ldmatrix lane addressing (byte offsets; identical layout to bf16 case)
    const int perm  = (lane & 7) << 4;
    const int arow  = warp_m * 64 + (lane & 7) + ((lane >> 3) & 1) * 8;   // + mt*16
    const int koffA = ((lane >> 4) & 1) << 4;                             // + q*32B
    const int brow0 = ((lane >> 4) & 1) * 32 + warp_n * 8 + (lane & 7);   // gates 0/1
    const int koffB = ((lane >> 3) & 1) << 4;

    float acc[4][4][4];   // [mt][gate][c]
    #pragma unroll
    for (int mt = 0; mt < 4; mt++)
        #pragma unroll
        for (int g = 0; g < 4; g++)
            #pragma unroll
            for (int c = 0; c < 4; c++) acc[mt][g][c] = 0.f;

    // prologue: prefetch chunks 0,1 (K=128 elements each)
    load_chunk(sb + SM_A(0), sb + SM_B(0), hin, Whh, m_base, jbase, 0, tid);   CP_COMMIT();
    load_chunk(sb + SM_A(1), sb + SM_B(1), hin, Whh, m_base, jbase, 128, tid); CP_COMMIT();

    for (int kc = 0; kc < 4; kc++) {
        if (kc == 3) { CP_WAIT0(); } else { CP_WAIT1(); }
        __syncthreads();

        if (kc + 2 < 4) {
            int s = (kc + 2) % 3;
            load_chunk(sb + SM_A(s), sb + SM_B(s), hin, Whh,
                       m_base, jbase, (kc + 2) * 128, tid);
            CP_COMMIT();
        }

        const uint32_t Ab = sb + SM_A(kc % 3);
        const uint32_t Bb = sb + SM_B(kc % 3);

        #pragma unroll
        for (int q = 0; q < 4; q++) {            // 4 x k32 per chunk (32B each)
            const int kq = q * 32;
            uint32_t bf[4][2];
            {
                uint32_t r[4];
                ldsm4(r, Bb + brow0 * 128 + ((kq + koffB) ^ perm));
                bf[0][0] = r[0]; bf[0][1] = r[1]; bf[1][0] = r[2]; bf[1][1] = r[3];
                ldsm4(r, Bb + (brow0 + 64) * 128 + ((kq + koffB) ^ perm));
                bf[2][0] = r[0]; bf[2][1] = r[1]; bf[3][0] = r[2]; bf[3][1] = r[3];
            }
            uint32_t af[4][4];
            #pragma unroll
            for (int mt = 0; mt < 4; mt++)
                ldsm4(af[mt], Ab + (arow + mt * 16) * 128 + ((kq + koffA) ^ perm));

            #pragma unroll
            for (int mt = 0; mt < 4; mt++)
                #pragma unroll
                for (int g = 0; g < 4; g++)
                    mma_fp8(acc[mt][g], af[mt], bf[g]);
        }
    }

    // ---------------- fused epilogue ----------------
    const int l2 = lane >> 2;
    const int u0 = warp_n * 8 + (lane & 3) * 2;

    #pragma unroll
    for (int mt = 0; mt < 4; mt++) {
        #pragma unroll
        for (int rh = 0; rh < 2; rh++) {
            const int mloc = warp_m * 64 + mt * 16 + l2 + rh * 8;
            const int m = m_base + mloc;
            const float4 xv = Xs[mloc];
            const size_t base = (size_t)m * HID + jbase + u0;
            const float2 cold = *(const float2*)(cio + base);
            float hn[2], cn[2];
            #pragma unroll
            for (int e = 0; e < 2; e++) {
                const int u = u0 + e;
                const int ci = rh * 2 + e;
                float4 wi = Wx[u], wf = Wx[32 + u], wg = Wx[64 + u], wo = Wx[96 + u];
                float pi = acc[mt][0][ci] * ACC_INV + Bs[u]      + wi.x*xv.x + wi.y*xv.y + wi.z*xv.z + wi.w*xv.w;
                float pf = acc[mt][1][ci] * ACC_INV + Bs[32 + u] + wf.x*xv.x + wf.y*xv.y + wf.z*xv.z + wf.w*xv.w;
                float pg = acc[mt][2][ci] * ACC_INV + Bs[64 + u] + wg.x*xv.x + wg.y*xv.y + wg.z*xv.z + wg.w*xv.w;
                float po = acc[mt][3][ci] * ACC_INV + Bs[96 + u] + wo.x*xv.x + wo.y*xv.y + wo.z*xv.z + wo.w*xv.w;
                float ig = sigm_(pi), fg = sigm_(pf);
                float gg = tanh_f(pg), og = sigm_(po);
                float cc = fg * ((e == 0) ? cold.x : cold.y) + ig * gg;
                cn[e] = cc;
                hn[e] = og * tanh_f(cc);
            }
            *(float2*)(cio + base) = make_float2(cn[0], cn[1]);
            *(uint16_t*)(hout + base) = f2_e4m3x2(hn[0] * H_SCALE, hn[1] * H_SCALE);
        }
    }
}

// ---------------------------------------------------------------------------
__global__ void combine_kernel(int fp, int n)
{
    int i = blockIdx.x * blockDim.x + threadIdx.x;
    if (i < n) {
        // both operands stored *16; sum keeps the *16 scale
        float ha = e4m3_f(g_h[(size_t)(fp * 2 + 0) * BH + i]);
        float hb = e4m3_f(g_h[(size_t)(fp * 2 + 1) * BH + i]);
        __nv_fp8_e4m3 q(ha + hb);
        g_hd[i] = *reinterpret_cast<uint8_t*>(&q);
        g_cd[i] = g_c[i] + g_c[BH + i];
    }
}

// ---------------------------------------------------------------------------
__global__ __launch_bounds__(256) void fc_kernel(
    const float* __restrict__ Wfc, const float* __restrict__ bfc,
    const float* __restrict__ Wemb, const float* __restrict__ bemb,
    float* __restrict__ out, int hping, int t, int L, int B)
{
    __shared__ float Wf[2 * HID];
    int tid = threadIdx.x;
    for (int i = tid; i < 2 * HID; i += 256) Wf[i] = Wfc[i];
    __syncthreads();

    int warp = tid >> 5, lane = tid & 31;
    int b = blockIdx.x * 8 + warp;
    if (b >= B) return;

    const uint8_t* hr = g_hd + (size_t)hping * BH + (size_t)b * HID;
    float s0 = 0.f, s1 = 0.f;
    #pragma unroll
    for (int k = lane; k < HID; k += 32) {
        float hv = e4m3_f(hr[k]);        // scaled by 16
        s0 += hv * Wf[k];
        s1 += hv * Wf[HID + k];
    }
    #pragma unroll
    for (int o = 16; o; o >>= 1) {
        s0 += __shfl_xor_sync(0xFFFFFFFFu, s0, o);
        s1 += __shfl_xor_sync(0xFFFFFFFFu, s1, o);
    }
    if (lane == 0) {
        float c0 = fmaxf(s0 * H_INV + bfc[0], 0.f);
        float c1 = fmaxf(s1 * H_INV + bfc[1], 0.f);
        #pragma unroll
        for (int k = 0; k < 4; k++)
            g_lastpos[b * 4 + k] = fmaxf(c0 * Wemb[k * 2 + 0] + c1 * Wemb[k * 2 + 1] + bemb[k], 0.f);
        float mx = fmaxf(c0, c1);
        float e0 = __expf(c0 - mx), e1 = __expf(c1 - mx);
        float inv = 1.f / (e0 + e1);
        out[(size_t)b * L * 2 + t * 2 + 0] = e0 * inv;
        out[(size_t)b * L * 2 + t * 2 + 1] = e1 * inv;
    }
}

// ---------------------------------------------------------------------------
extern "C" void kernel_launch(void* const* d_in, const int* in_sizes, int n_in,
                              void* d_out, int out_size)
{
    const float* speed = (const float*)d_in[0];
    const float* pos   = (const float*)d_in[1];
    const float* Ws_ih = (const float*)d_in[2];
    const float* Ws_hh = (const float*)d_in[3];
    const float* bs_ih = (const float*)d_in[4];
    const float* bs_hh = (const float*)d_in[5];
    const float* Wp_ih = (const float*)d_in[6];
    const float* Wp_hh = (const float*)d_in[7];
    const float* bp_ih = (const float*)d_in[8];
    const float* bp_hh = (const float*)d_in[9];
    const float* Wd_ih = (const float*)d_in[10];
    const float* Wd_hh = (const float*)d_in[11];
    const float* bd_ih = (const float*)d_in[12];
    const float* bd_hh = (const float*)d_in[13];
    const float* W_fc  = (const float*)d_in[14];
    const float* b_fc  = (const float*)d_in[15];
    const float* W_emb = (const float*)d_in[16];
    const float* b_emb = (const float*)d_in[17];
    float* out = (float*)d_out;

    const int T = 16;
    const int B = in_sizes[0] / (T * F_IN);
    const int L = out_size / (2 * B);

    static int smem_set = 0;
    if (!smem_set) {
        cudaFuncSetAttribute(lstm_mma_step, cudaFuncAttributeMaxDynamicSharedMemorySize, SM_TOTAL);
        smem_set = 1;
    }

    init_kernel<<<2048, 256>>>(Ws_hh, Wp_hh, Wd_hh);

    dim3 gs(HID / 32, B / 128, 2);
    for (int t = 0; t < T; t++) {
        StepParams p;
        p.xA = speed; p.xB = pos;
        p.x_stride = T * F_IN; p.x_off = t * F_IN;
        p.WihA = Ws_ih; p.WihB = Wp_ih;
        p.bihA = bs_ih; p.bihB = bp_ih;
        p.bhhA = bs_hh; p.bhhB = bp_hh;
        p.wsel = 0; p.ping = t & 1; p.is_dec = 0;
        lstm_mma_step<<<gs, 256, SM_TOTAL>>>(p);
    }

    int final_ping = ((T - 1) & 1) ^ 1;
    int n = B * HID;
    combine_kernel<<<(n + 255) / 256, 256>>>(final_ping, n);

    dim3 gd(HID / 32, B / 128, 1);
    for (int t = 0; t < L; t++) {
        StepParams p;
        if (t == 0) {
            p.xA = pos; p.xB = pos;
            p.x_stride = T * F_IN; p.x_off = (T - 1) * F_IN;
        } else {
            p.xA = nullptr; p.xB = nullptr;
            p.x_stride = F_IN; p.x_off = 0;
        }
        p.WihA = Wd_ih; p.WihB = Wd_ih;
        p.bihA = bd_ih; p.bihB = bd_ih;
        p.bhhA = bd_hh; p.bhhB = bd_hh;
        p.wsel = 2; p.ping = t & 1; p.is_dec = 1;
        lstm_mma_step<<<gd, 256, SM_TOTAL>>>(p);

        fc_kernel<<<(B + 7) / 8, 256>>>(W_fc, b_fc, W_emb, b_emb,
                                        out, (t + 1) & 1, t, L, B);
    }
}

// round 12
// speedup vs baseline: 1.1913x; 1.1913x over previous
#include <cuda_runtime.h>
#include <cuda_bf16.h>
#include <math.h>
#include <stdint.h>

// ---------------------------------------------------------------------------
// Intention_PS_LSTM on GB300 (sm_103 target -> mma.sync bf16 HMMA path).
// gates[8192,2048] = h[8192,512] @ Whh^T, per CTA: M=128, N=128(4g x 32u), K=512.
// 256 threads, 2 CTAs/SM, 3-stage cp.async pipe.
// Round 10: bf16 revert (fp8 regressed) + c-tile prefetch into dead smem stage.
// ---------------------------------------------------------------------------

#define HID   512
#define F_IN  4
#define MAXB  8192
#define BH    ((size_t)MAXB * HID)
#define WSZ   (4 * HID * HID)          // one Whh: 2048*512

#define SWZ(x) ((x) ^ ((((uint32_t)(x)) >> 3) & 0x70))

// smem byte offsets (tiles 1024-aligned)
#define SM_WX     0                    // float4[128]  = 2048
#define SM_BS     2048                 // float[128]   = 512
#define SM_XS     2560                 // float4[128]  = 2048
#define SM_A(s)   (8192  + (s) * 16384)    // 128 x 128B per stage
#define SM_B(s)   (57344 + (s) * 16384)    // 128 x 128B per stage
#define SM_C      SM_A(2)                  // c-tile reuses stage-2 A (dead after kc=5)
#define SM_TOTAL  106496

__device__ __align__(16) __nv_bfloat16 g_wb[3 * WSZ];   // bf16 Whh: s,p,d
__device__ __align__(16) __nv_bfloat16 g_h[4 * BH];     // encoder h: ping*2+z
__device__ __align__(16) float         g_c[2 * BH];     // encoder c: z
__device__ __align__(16) __nv_bfloat16 g_hd[2 * BH];    // decoder h ping-pong
__device__ __align__(16) float         g_cd[BH];        // decoder c
__device__ __align__(16) float         g_lastpos[MAXB * F_IN];

__device__ __forceinline__ float tanh_f(float x) {
    float y;
    asm("tanh.approx.f32 %0, %1;" : "=f"(y) : "f"(x));
    return y;
}
__device__ __forceinline__ float sigm_(float x) {
    return fmaf(tanh_f(0.5f * x), 0.5f, 0.5f);
}

__device__ __forceinline__ uint32_t smem_u32(const void* p) {
    uint32_t a;
    asm("{ .reg .u64 t; cvta.to.shared.u64 t, %1; cvt.u32.u64 %0, t; }" : "=r"(a) : "l"(p));
    return a;
}
__device__ __forceinline__ void cp16(uint32_t s, const void* g) {
    asm volatile("cp.async.cg.shared.global [%0], [%1], 16;" :: "r"(s), "l"(g));
}
#define CP_COMMIT() asm volatile("cp.async.commit_group;" ::: "memory")
#define CP_WAIT1()  asm volatile("cp.async.wait_group 1;" ::: "memory")
#define CP_WAIT0()  asm volatile("cp.async.wait_group 0;" ::: "memory")

__device__ __forceinline__ void ldsm4(uint32_t* r, uint32_t addr) {
    asm volatile("ldmatrix.sync.aligned.m8n8.x4.shared.b16 {%0,%1,%2,%3}, [%4];"
                 : "=r"(r[0]), "=r"(r[1]), "=r"(r[2]), "=r"(r[3]) : "r"(addr));
}
__device__ __forceinline__ void mma_bf16(float* d, const uint32_t* a, const uint32_t* b) {
    asm volatile("mma.sync.aligned.m16n8k16.row.col.f32.bf16.bf16.f32 "
                 "{%0,%1,%2,%3}, {%4,%5,%6,%7}, {%8,%9}, {%0,%1,%2,%3};"
                 : "+f"(d[0]), "+f"(d[1]), "+f"(d[2]), "+f"(d[3])
                 : "r"(a[0]), "r"(a[1]), "r"(a[2]), "r"(a[3]), "r"(b[0]), "r"(b[1]));
}

// ---------------------------------------------------------------------------
__global__ void init_kernel(const float* __restrict__ ws,
                            const float* __restrict__ wp,
                            const float* __restrict__ wd)
{
    size_t i = (size_t)blockIdx.x * blockDim.x + threadIdx.x;
    size_t stride = (size_t)gridDim.x * blockDim.x;
    for (size_t k = i; k < 3 * (size_t)WSZ; k += stride) {
        size_t w = k / WSZ, r = k % WSZ;
        const float* src = (w == 0) ? ws : (w == 1) ? wp : wd;
        g_wb[k] = __float2bfloat16(src[r]);
    }
    for (size_t k = i; k < 2 * BH; k += stride) {
        g_h[k] = __float2bfloat16(0.f);
        g_c[k] = 0.f;
    }
}

// ---------------------------------------------------------------------------
struct StepParams {
    const float* xA; const float* xB;   // per-z input; NULL => g_lastpos
    int x_stride; int x_off;
    const float* WihA; const float* WihB;
    const float* bihA; const float* bihB;
    const float* bhhA; const float* bhhB;
    int wsel;                           // Whh base: encoder 0 (+z), decoder 2
    int ping; int is_dec;
};

__device__ __forceinline__ void load_chunk(uint32_t Ab, uint32_t Bb,
                                           const __nv_bfloat16* __restrict__ hin,
                                           const __nv_bfloat16* __restrict__ Whh,
                                           int m_base, int jbase, int kf, int tid)
{
    #pragma unroll
    for (int it = 0; it < 4; it++) {                    // A: 128 rows x 8 x 16B
        int idx = tid + it * 256;
        int row = idx >> 3, c16 = idx & 7;
        cp16(Ab + SWZ(row * 128 + c16 * 16),
             hin + (size_t)(m_base + row) * HID + kf + c16 * 8);
    }
    #pragma unroll
    for (int it = 0; it < 4; it++) {                    // B: 128 rows x 8 x 16B
        int idx = tid + it * 256;
        int row = idx >> 3, c16 = idx & 7;
        int g = row >> 5, jj = row & 31;
        cp16(Bb + SWZ(row * 128 + c16 * 16),
             Whh + (size_t)(g * HID + jbase + jj) * HID + kf + c16 * 8);
    }
}

__global__ __launch_bounds__(256, 2) void lstm_mma_step(StepParams p)
{
    extern __shared__ char smem[];
    const uint32_t sb = smem_u32(smem);
    const int tid  = threadIdx.x;
    const int wid  = tid >> 5, lane = tid & 31;
    const int z    = blockIdx.z;
    const int warp_m = wid & 1;        // 2 m-groups of 64 rows
    const int warp_n = wid >> 1;       // 4 n-groups of 8 units

    const float* __restrict__ Wih = z ? p.WihB : p.WihA;
    const float* __restrict__ bih = z ? p.bihB : p.bihA;
    const float* __restrict__ bhh = z ? p.bhhB : p.bhhA;
    const float* __restrict__ xin = z ? p.xB : p.xA;
    const __nv_bfloat16* __restrict__ Whh = g_wb + (size_t)(p.wsel + z) * WSZ;

    const __nv_bfloat16* __restrict__ hin;
    __nv_bfloat16* __restrict__ hout;
    float* __restrict__ cio;
    if (p.is_dec) {
        hin  = g_hd + (size_t)p.ping * BH;
        hout = g_hd + (size_t)(p.ping ^ 1) * BH;
        cio  = g_cd;
        if (!xin) xin = g_lastpos;
    } else {
        hin  = g_h + (size_t)(p.ping * 2 + z) * BH;
        hout = g_h + (size_t)((p.ping ^ 1) * 2 + z) * BH;
        cio  = g_c + (size_t)z * BH;
    }

    const int m_base = blockIdx.y * 128;
    const int jbase  = blockIdx.x * 32;

    float4* Wx = (float4*)(smem + SM_WX);
    float*  Bs = (float*)(smem + SM_BS);
    float4* Xs = (float4*)(smem + SM_XS);

    if (tid < 128) {
        int g = tid >> 5, u = tid & 31;
        int gr = g * HID + jbase + u;
        Bs[tid] = bih[gr] + bhh[gr];
        Wx[tid] = *(const float4*)(Wih + (size_t)gr * F_IN);
    } else {
        int r = tid - 128;
        Xs[r] = *(const float4*)(xin + (size_t)(m_base + r) * p.x_stride + p.x_off);
    }

    // ldmatrix lane addressing
    const int perm  = (lane & 7) << 4;
    const int arow  = warp_m * 64 + (lane & 7) + ((lane >> 3) & 1) * 8;   // + mt*16
    const int koffA = ((lane >> 4) & 1) << 4;                             // + q*32
    const int brow0 = ((lane >> 4) & 1) * 32 + warp_n * 8 + (lane & 7);   // gates 0/1
    const int koffB = ((lane >> 3) & 1) << 4;

    float acc[4][4][4];   // [mt][gate][c]
    #pragma unroll
    for (int mt = 0; mt < 4; mt++)
        #pragma unroll
        for (int g = 0; g < 4; g++)
            #pragma unroll
            for (int c = 0; c < 4; c++) acc[mt][g][c] = 0.f;

    // prologue: prefetch chunks 0,1 into stages 0,1
    load_chunk(sb + SM_A(0), sb + SM_B(0), hin, Whh, m_base, jbase, 0, tid);  CP_COMMIT();
    load_chunk(sb + SM_A(1), sb + SM_B(1), hin, Whh, m_base, jbase, 64, tid); CP_COMMIT();

    for (int kc = 0; kc < 8; kc++) {
        if (kc == 7) { CP_WAIT0(); } else { CP_WAIT1(); }
        __syncthreads();

        if (kc + 2 < 8) {
            // prefetch chunk kc+2 into the stage freed at the barrier above
            int s = (kc + 2) % 3;
            load_chunk(sb + SM_A(s), sb + SM_B(s), hin, Whh,
                       m_base, jbase, (kc + 2) * 64, tid);
            CP_COMMIT();
        } else if (kc == 6) {
            // stage-2 A buffer is dead (last read kc=5, fenced by this barrier):
            // prefetch this tile's c [128 x 32 f32 = 128 x 128B] into it.
            #pragma unroll
            for (int it = 0; it < 4; it++) {
                int idx = tid + it * 256;
                int row = idx >> 3, c16 = idx & 7;
                cp16(sb + SM_C + SWZ(row * 128 + c16 * 16),
                     cio + (size_t)(m_base + row) * HID + jbase + c16 * 4);
            }
            CP_COMMIT();
        }

        const uint32_t Ab = sb + SM_A(kc % 3);
        const uint32_t Bb = sb + SM_B(kc % 3);

        #pragma unroll
        for (int q = 0; q < 4; q++) {            // 4 x k16 per chunk
            const int kq = q * 32;
            uint32_t bf[4][2];
            {
                uint32_t r[4];
                ldsm4(r, Bb + brow0 * 128 + ((kq + koffB) ^ perm));
                bf[0][0] = r[0]; bf[0][1] = r[1]; bf[1][0] = r[2]; bf[1][1] = r[3];
                ldsm4(r, Bb + (brow0 + 64) * 128 + ((kq + koffB) ^ perm));
                bf[2][0] = r[0]; bf[2][1] = r[1]; bf[3][0] = r[2]; bf[3][1] = r[3];
            }
            uint32_t af[4][4];
            #pragma unroll
            for (int mt = 0; mt < 4; mt++)
                ldsm4(af[mt], Ab + (arow + mt * 16) * 128 + ((kq + koffA) ^ perm));

            #pragma unroll
            for (int mt = 0; mt < 4; mt++)
                #pragma unroll
                for (int g = 0; g < 4; g++)
                    mma_bf16(acc[mt][g], af[mt], bf[g]);
        }
    }

    // ---------------- fused epilogue (c read from hot smem) ----------------
    const int l2 = lane >> 2;
    const int u0 = warp_n * 8 + (lane & 3) * 2;

    #pragma unroll
    for (int mt = 0; mt < 4; mt++) {
        #pragma unroll
        for (int rh = 0; rh < 2; rh++) {
            const int mloc = warp_m * 64 + mt * 16 + l2 + rh * 8;
            const int m = m_base + mloc;
            const float4 xv = Xs[mloc];
            const size_t base = (size_t)m * HID + jbase + u0;
            const float2 cold = *(const float2*)(smem + SM_C + SWZ(mloc * 128 + u0 * 4));
            float hn[2], cn[2];
            #pragma unroll
            for (int e = 0; e < 2; e++) {
                const int u = u0 + e;
                const int ci = rh * 2 + e;
                float4 wi = Wx[u], wf = Wx[32 + u], wg = Wx[64 + u], wo = Wx[96 + u];
                float pi = acc[mt][0][ci] + Bs[u]      + wi.x*xv.x + wi.y*xv.y + wi.z*xv.z + wi.w*xv.w;
                float pf = acc[mt][1][ci] + Bs[32 + u] + wf.x*xv.x + wf.y*xv.y + wf.z*xv.z + wf.w*xv.w;
                float pg = acc[mt][2][ci] + Bs[64 + u] + wg.x*xv.x + wg.y*xv.y + wg.z*xv.z + wg.w*xv.w;
                float po = acc[mt][3][ci] + Bs[96 + u] + wo.x*xv.x + wo.y*xv.y + wo.z*xv.z + wo.w*xv.w;
                float ig = sigm_(pi), fg = sigm_(pf);
                float gg = tanh_f(pg), og = sigm_(po);
                float cc = fg * ((e == 0) ? cold.x : cold.y) + ig * gg;
                cn[e] = cc;
                hn[e] = og * tanh_f(cc);
            }
            *(float2*)(cio + base) = make_float2(cn[0], cn[1]);
            *(__nv_bfloat162*)(hout + base) =
                __nv_bfloat162(__float2bfloat16(hn[0]), __float2bfloat16(hn[1]));
        }
    }
}

// ---------------------------------------------------------------------------
__global__ void combine_kernel(int fp, int n)
{
    int i = blockIdx.x * blockDim.x + threadIdx.x;
    if (i < n) {
        float ha = __bfloat162float(g_h[(size_t)(fp * 2 + 0) * BH + i]);
        float hb = __bfloat162float(g_h[(size_t)(fp * 2 + 1) * BH + i]);
        g_hd[i] = __float2bfloat16(ha + hb);
        g_cd[i] = g_c[i] + g_c[BH + i];
    }
}

// ---------------------------------------------------------------------------
__global__ __launch_bounds__(256) void fc_kernel(
    const float* __restrict__ Wfc, const float* __restrict__ bfc,
    const float* __restrict__ Wemb, const float* __restrict__ bemb,
    float* __restrict__ out, int hping, int t, int L, int B)
{
    __shared__ float Wf[2 * HID];
    int tid = threadIdx.x;
    for (int i = tid; i < 2 * HID; i += 256) Wf[i] = Wfc[i];
    __syncthreads();

    int warp = tid >> 5, lane = tid & 31;
    int b = blockIdx.x * 8 + warp;
    if (b >= B) return;

    const __nv_bfloat16* hr = g_hd + (size_t)hping * BH + (size_t)b * HID;
    float s0 = 0.f, s1 = 0.f;
    #pragma unroll
    for (int k = lane; k < HID; k += 32) {
        float hv = __bfloat162float(hr[k]);
        s0 += hv * Wf[k];
        s1 += hv * Wf[HID + k];
    }
    #pragma unroll
    for (int o = 16; o; o >>= 1) {
        s0 += __shfl_xor_sync(0xFFFFFFFFu, s0, o);
        s1 += __shfl_xor_sync(0xFFFFFFFFu, s1, o);
    }
    if (lane == 0) {
        float c0 = fmaxf(s0 + bfc[0], 0.f);
        float c1 = fmaxf(s1 + bfc[1], 0.f);
        #pragma unroll
        for (int k = 0; k < 4; k++)
            g_lastpos[b * 4 + k] = fmaxf(c0 * Wemb[k * 2 + 0] + c1 * Wemb[k * 2 + 1] + bemb[k], 0.f);
        float mx = fmaxf(c0, c1);
        float e0 = __expf(c0 - mx), e1 = __expf(c1 - mx);
        float inv = 1.f / (e0 + e1);
        out[(size_t)b * L * 2 + t * 2 + 0] = e0 * inv;
        out[(size_t)b * L * 2 + t * 2 + 1] = e1 * inv;
    }
}

// ---------------------------------------------------------------------------
extern "C" void kernel_launch(void* const* d_in, const int* in_sizes, int n_in,
                              void* d_out, int out_size)
{
    const float* speed = (const float*)d_in[0];
    const float* pos   = (const float*)d_in[1];
    const float* Ws_ih = (const float*)d_in[2];
    const float* Ws_hh = (const float*)d_in[3];
    const float* bs_ih = (const float*)d_in[4];
    const float* bs_hh = (const float*)d_in[5];
    const float* Wp_ih = (const float*)d_in[6];
    const float* Wp_hh = (const float*)d_in[7];
    const float* bp_ih = (const float*)d_in[8];
    const float* bp_hh = (const float*)d_in[9];
    const float* Wd_ih = (const float*)d_in[10];
    const float* Wd_hh = (const float*)d_in[11];
    const float* bd_ih = (const float*)d_in[12];
    const float* bd_hh = (const float*)d_in[13];
    const float* W_fc  = (const float*)d_in[14];
    const float* b_fc  = (const float*)d_in[15];
    const float* W_emb = (const float*)d_in[16];
    const float* b_emb = (const float*)d_in[17];
    float* out = (float*)d_out;

    const int T = 16;
    const int B = in_sizes[0] / (T * F_IN);
    const int L = out_size / (2 * B);

    static int smem_set = 0;
    if (!smem_set) {
        cudaFuncSetAttribute(lstm_mma_step, cudaFuncAttributeMaxDynamicSharedMemorySize, SM_TOTAL);
        smem_set = 1;
    }

    init_kernel<<<2048, 256>>>(Ws_hh, Wp_hh, Wd_hh);

    dim3 gs(HID / 32, B / 128, 2);
    for (int t = 0; t < T; t++) {
        StepParams p;
        p.xA = speed; p.xB = pos;
        p.x_stride = T * F_IN; p.x_off = t * F_IN;
        p.WihA = Ws_ih; p.WihB = Wp_ih;
        p.bihA = bs_ih; p.bihB = bp_ih;
        p.bhhA = bs_hh; p.bhhB = bp_hh;
        p.wsel = 0; p.ping = t & 1; p.is_dec = 0;
        lstm_mma_step<<<gs, 256, SM_TOTAL>>>(p);
    }

    int final_ping = ((T - 1) & 1) ^ 1;
    int n = B * HID;
    combine_kernel<<<(n + 255) / 256, 256>>>(final_ping, n);

    dim3 gd(HID / 32, B / 128, 1);
    for (int t = 0; t < L; t++) {
        StepParams p;
        if (t == 0) {
            p.xA = pos; p.xB = pos;
            p.x_stride = T * F_IN; p.x_off = (T - 1) * F_IN;
        } else {
            p.xA = nullptr; p.xB = nullptr;
            p.x_stride = F_IN; p.x_off = 0;
        }
        p.WihA = Wd_ih; p.WihB = Wd_ih;
        p.bihA = bd_ih; p.bihB = bd_ih;
        p.bhhA = bd_hh; p.bhhB = bd_hh;
        p.wsel = 2; p.ping = t & 1; p.is_dec = 1;
        lstm_mma_step<<<gd, 256, SM_TOTAL>>>(p);

        fc_kernel<<<(B + 7) / 8, 256>>>(W_fc, b_fc, W_emb, b_emb,
                                        out, (t + 1) & 1, t, L, B);
    }
}

// round 13
// speedup vs baseline: 1.2697x; 1.0658x over previous
#include <cuda_runtime.h>
#include <cuda_bf16.h>
#include <math.h>
#include <stdint.h>

// ---------------------------------------------------------------------------
// Intention_PS_LSTM on GB300 (sm_103 target -> mma.sync bf16 HMMA path).
// gates[8192,2048] = h[8192,512] @ Whh^T, per CTA: M=128, N=128(4g x 32u), K=512.
// 256 threads, 2 CTAs/SM, 3-stage cp.async ring.
// Round 13: __syncthreads-per-chunk replaced by mbarrier full/empty ring
// (cp.async.mbarrier.arrive.noinc) -> warps may skew up to 2 chunks.
// ---------------------------------------------------------------------------

#define HID   512
#define F_IN  4
#define MAXB  8192
#define BH    ((size_t)MAXB * HID)
#define WSZ   (4 * HID * HID)          // one Whh: 2048*512

#define SWZ(x) ((x) ^ ((((uint32_t)(x)) >> 3) & 0x70))

// smem byte offsets (tiles 1024-aligned)
#define SM_WX     0                    // float4[128]  = 2048
#define SM_BS     2048                 // float[128]   = 512
#define SM_XS     2560                 // float4[128]  = 2048
#define SM_MB     4608                 // full[3] @ +0, empty[3] @ +24  (48 B)
#define SM_A(s)   (8192  + (s) * 16384)    // 128 x 128B per stage
#define SM_B(s)   (57344 + (s) * 16384)    // 128 x 128B per stage
#define SM_C      SM_A(2)                  // c-tile reuses stage-2 A (3rd phase)
#define SM_TOTAL  106496

__device__ __align__(16) __nv_bfloat16 g_wb[3 * WSZ];   // bf16 Whh: s,p,d
__device__ __align__(16) __nv_bfloat16 g_h[4 * BH];     // encoder h: ping*2+z
__device__ __align__(16) float         g_c[2 * BH];     // encoder c: z
__device__ __align__(16) __nv_bfloat16 g_hd[2 * BH];    // decoder h ping-pong
__device__ __align__(16) float         g_cd[BH];        // decoder c
__device__ __align__(16) float         g_lastpos[MAXB * F_IN];

__device__ __forceinline__ float tanh_f(float x) {
    float y;
    asm("tanh.approx.f32 %0, %1;" : "=f"(y) : "f"(x));
    return y;
}
__device__ __forceinline__ float sigm_(float x) {
    return fmaf(tanh_f(0.5f * x), 0.5f, 0.5f);
}

__device__ __forceinline__ uint32_t smem_u32(const void* p) {
    uint32_t a;
    asm("{ .reg .u64 t; cvta.to.shared.u64 t, %1; cvt.u32.u64 %0, t; }" : "=r"(a) : "l"(p));
    return a;
}
__device__ __forceinline__ void cp16(uint32_t s, const void* g) {
    asm volatile("cp.async.cg.shared.global [%0], [%1], 16;" :: "r"(s), "l"(g));
}

#define MBAR_INIT(a, n) asm volatile("mbarrier.init.shared.b64 [%0], %1;" :: "r"(a), "r"(n) : "memory")
#define MBAR_ARRIVE(a)  asm volatile("mbarrier.arrive.shared.b64 _, [%0];" :: "r"(a) : "memory")
#define CPASYNC_ARRIVE(a) asm volatile("cp.async.mbarrier.arrive.noinc.shared.b64 [%0];" :: "r"(a) : "memory")
#define MBAR_WAIT(a, ph) do {                                                          \
    uint32_t _m = (a), _p = (ph), _d;                                                  \
    asm volatile("{ .reg .pred p; mbarrier.try_wait.parity.acquire.cta.shared::cta.b64 p, [%1], %2; selp.b32 %0,1,0,p; }" \
                 : "=r"(_d) : "r"(_m), "r"(_p) : "memory");                            \
    if (!_d) { asm volatile("{ .reg .pred P1; W%=: mbarrier.try_wait.parity.acquire.cta.shared::cta.b64 P1, [%0], %1, 0x989680; @P1 bra.uni D%=; bra.uni W%=; D%=: }" \
                 :: "r"(_m), "r"(_p) : "memory"); } } while (0)

__device__ __forceinline__ void ldsm4(uint32_t* r, uint32_t addr) {
    asm volatile("ldmatrix.sync.aligned.m8n8.x4.shared.b16 {%0,%1,%2,%3}, [%4];"
                 : "=r"(r[0]), "=r"(r[1]), "=r"(r[2]), "=r"(r[3]) : "r"(addr));
}
__device__ __forceinline__ void mma_bf16(float* d, const uint32_t* a, const uint32_t* b) {
    asm volatile("mma.sync.aligned.m16n8k16.row.col.f32.bf16.bf16.f32 "
                 "{%0,%1,%2,%3}, {%4,%5,%6,%7}, {%8,%9}, {%0,%1,%2,%3};"
                 : "+f"(d[0]), "+f"(d[1]), "+f"(d[2]), "+f"(d[3])
                 : "r"(a[0]), "r"(a[1]), "r"(a[2]), "r"(a[3]), "r"(b[0]), "r"(b[1]));
}

// ---------------------------------------------------------------------------
__global__ void init_kernel(const float* __restrict__ ws,
                            const float* __restrict__ wp,
                            const float* __restrict__ wd)
{
    size_t i = (size_t)blockIdx.x * blockDim.x + threadIdx.x;
    size_t stride = (size_t)gridDim.x * blockDim.x;
    for (size_t k = i; k < 3 * (size_t)WSZ; k += stride) {
        size_t w = k / WSZ, r = k % WSZ;
        const float* src = (w == 0) ? ws : (w == 1) ? wp : wd;
        g_wb[k] = __float2bfloat16(src[r]);
    }
    for (size_t k = i; k < 2 * BH; k += stride) {
        g_h[k] = __float2bfloat16(0.f);
        g_c[k] = 0.f;
    }
}

// ---------------------------------------------------------------------------
struct StepParams {
    const float* xA; const float* xB;   // per-z input; NULL => g_lastpos
    int x_stride; int x_off;
    const float* WihA; const float* WihB;
    const float* bihA; const float* bihB;
    const float* bhhA; const float* bhhB;
    int wsel;                           // Whh base: encoder 0 (+z), decoder 2
    int ping; int is_dec;
};

__device__ __forceinline__ void load_chunk(uint32_t Ab, uint32_t Bb,
                                           const __nv_bfloat16* __restrict__ hin,
                                           const __nv_bfloat16* __restrict__ Whh,
                                           int m_base, int jbase, int kf, int tid)
{
    #pragma unroll
    for (int it = 0; it < 4; it++) {                    // A: 128 rows x 8 x 16B
        int idx = tid + it * 256;
        int row = idx >> 3, c16 = idx & 7;
        cp16(Ab + SWZ(row * 128 + c16 * 16),
             hin + (size_t)(m_base + row) * HID + kf + c16 * 8);
    }
    #pragma unroll
    for (int it = 0; it < 4; it++) {                    // B: 128 rows x 8 x 16B
        int idx = tid + it * 256;
        int row = idx >> 3, c16 = idx & 7;
        int g = row >> 5, jj = row & 31;
        cp16(Bb + SWZ(row * 128 + c16 * 16),
             Whh + (size_t)(g * HID + jbase + jj) * HID + kf + c16 * 8);
    }
}

__global__ __launch_bounds__(256, 2) void lstm_mma_step(StepParams p)
{
    extern __shared__ char smem[];
    const uint32_t sb = smem_u32(smem);
    const int tid  = threadIdx.x;
    const int wid  = tid >> 5, lane = tid & 31;
    const int z    = blockIdx.z;
    const int warp_m = wid & 1;        // 2 m-groups of 64 rows
    const int warp_n = wid >> 1;       // 4 n-groups of 8 units

    const float* __restrict__ Wih = z ? p.WihB : p.WihA;
    const float* __restrict__ bih = z ? p.bihB : p.bihA;
    const float* __restrict__ bhh = z ? p.bhhB : p.bhhA;
    const float* __restrict__ xin = z ? p.xB : p.xA;
    const __nv_bfloat16* __restrict__ Whh = g_wb + (size_t)(p.wsel + z) * WSZ;

    const __nv_bfloat16* __restrict__ hin;
    __nv_bfloat16* __restrict__ hout;
    float* __restrict__ cio;
    if (p.is_dec) {
        hin  = g_hd + (size_t)p.ping * BH;
        hout = g_hd + (size_t)(p.ping ^ 1) * BH;
        cio  = g_cd;
        if (!xin) xin = g_lastpos;
    } else {
        hin  = g_h + (size_t)(p.ping * 2 + z) * BH;
        hout = g_h + (size_t)((p.ping ^ 1) * 2 + z) * BH;
        cio  = g_c + (size_t)z * BH;
    }

    const int m_base = blockIdx.y * 128;
    const int jbase  = blockIdx.x * 32;

    float4* Wx = (float4*)(smem + SM_WX);
    float*  Bs = (float*)(smem + SM_BS);
    float4* Xs = (float4*)(smem + SM_XS);

    if (tid == 0) {
        #pragma unroll
        for (int s2 = 0; s2 < 3; s2++) {
            MBAR_INIT(sb + SM_MB + s2 * 8, 256);        // full[s2]
            MBAR_INIT(sb + SM_MB + 24 + s2 * 8, 256);   // empty[s2]
        }
    }
    if (tid < 128) {
        int g = tid >> 5, u = tid & 31;
        int gr = g * HID + jbase + u;
        Bs[tid] = bih[gr] + bhh[gr];
        Wx[tid] = *(const float4*)(Wih + (size_t)gr * F_IN);
    } else {
        int r = tid - 128;
        Xs[r] = *(const float4*)(xin + (size_t)(m_base + r) * p.x_stride + p.x_off);
    }
    __syncthreads();   // mbar init + Wx/Bs/Xs visibility (only CTA-wide barrier)

    // ldmatrix lane addressing
    const int perm  = (lane & 7) << 4;
    const int arow  = warp_m * 64 + (lane & 7) + ((lane >> 3) & 1) * 8;   // + mt*16
    const int koffA = ((lane >> 4) & 1) << 4;                             // + q*32
    const int brow0 = ((lane >> 4) & 1) * 32 + warp_n * 8 + (lane & 7);   // gates 0/1
    const int koffB = ((lane >> 3) & 1) << 4;

    float acc[4][4][4];   // [mt][gate][c]
    #pragma unroll
    for (int mt = 0; mt < 4; mt++)
        #pragma unroll
        for (int g = 0; g < 4; g++)
            #pragma unroll
            for (int c = 0; c < 4; c++) acc[mt][g][c] = 0.f;

    // prologue: prefetch chunks 0,1 into stages 0,1 (async-arrive on full)
    load_chunk(sb + SM_A(0), sb + SM_B(0), hin, Whh, m_base, jbase, 0, tid);
    CPASYNC_ARRIVE(sb + SM_MB + 0);
    load_chunk(sb + SM_A(1), sb + SM_B(1), hin, Whh, m_base, jbase, 64, tid);
    CPASYNC_ARRIVE(sb + SM_MB + 8);

    #pragma unroll
    for (int kc = 0; kc < 8; kc++) {
        const int s = kc % 3;

        // ---- producer: chunk kc+2 (or c-tile at kc==6) ----
        if (kc + 2 < 8) {
            const int sp = (kc + 2) % 3;
            if (kc + 2 >= 3)
                MBAR_WAIT(sb + SM_MB + 24 + sp * 8, ((kc - 1) / 3) & 1);
            load_chunk(sb + SM_A(sp), sb + SM_B(sp), hin, Whh,
                       m_base, jbase, (kc + 2) * 64, tid);
            CPASYNC_ARRIVE(sb + SM_MB + sp * 8);
        } else if (kc == 6) {
            // stage-2 A region: 3rd producer phase = this tile's c [128 x 128B]
            MBAR_WAIT(sb + SM_MB + 24 + 16, 1);         // empty[2] use #1
            #pragma unroll
            for (int it = 0; it < 4; it++) {
                int idx = tid + it * 256;
                int row = idx >> 3, c16 = idx & 7;
                cp16(sb + SM_C + SWZ(row * 128 + c16 * 16),
                     cio + (size_t)(m_base + row) * HID + jbase + c16 * 4);
            }
            CPASYNC_ARRIVE(sb + SM_MB + 16);            // full[2] use #2
        }

        // ---- consumer: chunk kc ----
        MBAR_WAIT(sb + SM_MB + s * 8, (kc / 3) & 1);

        const uint32_t Ab = sb + SM_A(s);
        const uint32_t Bb = sb + SM_B(s);

        #pragma unroll
        for (int q = 0; q < 4; q++) {            // 4 x k16 per chunk
            const int kq = q * 32;
            uint32_t bf[4][2];
            {
                uint32_t r[4];
                ldsm4(r, Bb + brow0 * 128 + ((kq + koffB) ^ perm));
                bf[0][0] = r[0]; bf[0][1] = r[1]; bf[1][0] = r[2]; bf[1][1] = r[3];
                ldsm4(r, Bb + (brow0 + 64) * 128 + ((kq + koffB) ^ perm));
                bf[2][0] = r[0]; bf[2][1] = r[1]; bf[3][0] = r[2]; bf[3][1] = r[3];
            }
            uint32_t af[4][4];
            #pragma unroll
            for (int mt = 0; mt < 4; mt++)
                ldsm4(af[mt], Ab + (arow + mt * 16) * 128 + ((kq + koffA) ^ perm));

            #pragma unroll
            for (int mt = 0; mt < 4; mt++)
                #pragma unroll
                for (int g = 0; g < 4; g++)
                    mma_bf16(acc[mt][g], af[mt], bf[g]);
        }
        MBAR_ARRIVE(sb + SM_MB + 24 + s * 8);    // empty[s]
    }

    // ---------------- fused epilogue (c read from hot smem) ----------------
    MBAR_WAIT(sb + SM_MB + 16, 0);               // full[2] use #2 (c ready)

    const int l2 = lane >> 2;
    const int u0 = warp_n * 8 + (lane & 3) * 2;

    #pragma unroll
    for (int mt = 0; mt < 4; mt++) {
        #pragma unroll
        for (int rh = 0; rh < 2; rh++) {
            const int mloc = warp_m * 64 + mt * 16 + l2 + rh * 8;
            const int m = m_base + mloc;
            const float4 xv = Xs[mloc];
            const size_t base = (size_t)m * HID + jbase + u0;
            const float2 cold = *(const float2*)(smem + SM_C + SWZ(mloc * 128 + u0 * 4));
            float hn[2], cn[2];
            #pragma unroll
            for (int e = 0; e < 2; e++) {
                const int u = u0 + e;
                const int ci = rh * 2 + e;
                float4 wi = Wx[u], wf = Wx[32 + u], wg = Wx[64 + u], wo = Wx[96 + u];
                float pi = acc[mt][0][ci] + Bs[u]      + wi.x*xv.x + wi.y*xv.y + wi.z*xv.z + wi.w*xv.w;
                float pf = acc[mt][1][ci] + Bs[32 + u] + wf.x*xv.x + wf.y*xv.y + wf.z*xv.z + wf.w*xv.w;
                float pg = acc[mt][2][ci] + Bs[64 + u] + wg.x*xv.x + wg.y*xv.y + wg.z*xv.z + wg.w*xv.w;
                float po = acc[mt][3][ci] + Bs[96 + u] + wo.x*xv.x + wo.y*xv.y + wo.z*xv.z + wo.w*xv.w;
                float ig = sigm_(pi), fg = sigm_(pf);
                float gg = tanh_f(pg), og = sigm_(po);
                float cc = fg * ((e == 0) ? cold.x : cold.y) + ig * gg;
                cn[e] = cc;
                hn[e] = og * tanh_f(cc);
            }
            *(float2*)(cio + base) = make_float2(cn[0], cn[1]);
            *(__nv_bfloat162*)(hout + base) =
                __nv_bfloat162(__float2bfloat16(hn[0]), __float2bfloat16(hn[1]));
        }
    }
}

// ---------------------------------------------------------------------------
__global__ void combine_kernel(int fp, int n)
{
    int i = blockIdx.x * blockDim.x + threadIdx.x;
    if (i < n) {
        float ha = __bfloat162float(g_h[(size_t)(fp * 2 + 0) * BH + i]);
        float hb = __bfloat162float(g_h[(size_t)(fp * 2 + 1) * BH + i]);
        g_hd[i] = __float2bfloat16(ha + hb);
        g_cd[i] = g_c[i] + g_c[BH + i];
    }
}

// ---------------------------------------------------------------------------
__global__ __launch_bounds__(256) void fc_kernel(
    const float* __restrict__ Wfc, const float* __restrict__ bfc,
    const float* __restrict__ Wemb, const float* __restrict__ bemb,
    float* __restrict__ out, int hping, int t, int L, int B)
{
    __shared__ float Wf[2 * HID];
    int tid = threadIdx.x;
    for (int i = tid; i < 2 * HID; i += 256) Wf[i] = Wfc[i];
    __syncthreads();

    int warp = tid >> 5, lane = tid & 31;
    int b = blockIdx.x * 8 + warp;
    if (b >= B) return;

    const __nv_bfloat16* hr = g_hd + (size_t)hping * BH + (size_t)b * HID;
    float s0 = 0.f, s1 = 0.f;
    #pragma unroll
    for (int k = lane; k < HID; k += 32) {
        float hv = __bfloat162float(hr[k]);
        s0 += hv * Wf[k];
        s1 += hv * Wf[HID + k];
    }
    #pragma unroll
    for (int o = 16; o; o >>= 1) {
        s0 += __shfl_xor_sync(0xFFFFFFFFu, s0, o);
        s1 += __shfl_xor_sync(0xFFFFFFFFu, s1, o);
    }
    if (lane == 0) {
        float c0 = fmaxf(s0 + bfc[0], 0.f);
        float c1 = fmaxf(s1 + bfc[1], 0.f);
        #pragma unroll
        for (int k = 0; k < 4; k++)
            g_lastpos[b * 4 + k] = fmaxf(c0 * Wemb[k * 2 + 0] + c1 * Wemb[k * 2 + 1] + bemb[k], 0.f);
        float mx = fmaxf(c0, c1);
        float e0 = __expf(c0 - mx), e1 = __expf(c1 - mx);
        float inv = 1.f / (e0 + e1);
        out[(size_t)b * L * 2 + t * 2 + 0] = e0 * inv;
        out[(size_t)b * L * 2 + t * 2 + 1] = e1 * inv;
    }
}

// ---------------------------------------------------------------------------
extern "C" void kernel_launch(void* const* d_in, const int* in_sizes, int n_in,
                              void* d_out, int out_size)
{
    const float* speed = (const float*)d_in[0];
    const float* pos   = (const float*)d_in[1];
    const float* Ws_ih = (const float*)d_in[2];
    const float* Ws_hh = (const float*)d_in[3];
    const float* bs_ih = (const float*)d_in[4];
    const float* bs_hh = (const float*)d_in[5];
    const float* Wp_ih = (const float*)d_in[6];
    const float* Wp_hh = (const float*)d_in[7];
    const float* bp_ih = (const float*)d_in[8];
    const float* bp_hh = (const float*)d_in[9];
    const float* Wd_ih = (const float*)d_in[10];
    const float* Wd_hh = (const float*)d_in[11];
    const float* bd_ih = (const float*)d_in[12];
    const float* bd_hh = (const float*)d_in[13];
    const float* W_fc  = (const float*)d_in[14];
    const float* b_fc  = (const float*)d_in[15];
    const float* W_emb = (const float*)d_in[16];
    const float* b_emb = (const float*)d_in[17];
    float* out = (float*)d_out;

    const int T = 16;
    const int B = in_sizes[0] / (T * F_IN);
    const int L = out_size / (2 * B);

    static int smem_set = 0;
    if (!smem_set) {
        cudaFuncSetAttribute(lstm_mma_step, cudaFuncAttributeMaxDynamicSharedMemorySize, SM_TOTAL);
        smem_set = 1;
    }

    init_kernel<<<2048, 256>>>(Ws_hh, Wp_hh, Wd_hh);

    dim3 gs(HID / 32, B / 128, 2);
    for (int t = 0; t < T; t++) {
        StepParams p;
        p.xA = speed; p.xB = pos;
        p.x_stride = T * F_IN; p.x_off = t * F_IN;
        p.WihA = Ws_ih; p.WihB = Wp_ih;
        p.bihA = bs_ih; p.bihB = bp_ih;
        p.bhhA = bs_hh; p.bhhB = bp_hh;
        p.wsel = 0; p.ping = t & 1; p.is_dec = 0;
        lstm_mma_step<<<gs, 256, SM_TOTAL>>>(p);
    }

    int final_ping = ((T - 1) & 1) ^ 1;
    int n = B * HID;
    combine_kernel<<<(n + 255) / 256, 256>>>(final_ping, n);

    dim3 gd(HID / 32, B / 128, 1);
    for (int t = 0; t < L; t++) {
        StepParams p;
        if (t == 0) {
            p.xA = pos; p.xB = pos;
            p.x_stride = T * F_IN; p.x_off = (T - 1) * F_IN;
        } else {
            p.xA = nullptr; p.xB = nullptr;
            p.x_stride = F_IN; p.x_off = 0;
        }
        p.WihA = Wd_ih; p.WihB = Wd_ih;
        p.bihA = bd_ih; p.bihB = bd_ih;
        p.bhhA = bd_hh; p.bhhB = bd_hh;
        p.wsel = 2; p.ping = t & 1; p.is_dec = 1;
        lstm_mma_step<<<gd, 256, SM_TOTAL>>>(p);

        fc_kernel<<<(B + 7) / 8, 256>>>(W_fc, b_fc, W_emb, b_emb,
                                        out, (t + 1) & 1, t, L, B);
    }
}